// round 14
// baseline (speedup 1.0000x reference)
#include <cuda_runtime.h>

namespace {
constexpr int Hn = 1024;   // time steps

__device__ __forceinline__ float tanh_fast(float x){ float r; asm("tanh.approx.f32 %0, %1;" : "=f"(r) : "f"(x)); return r; }
__device__ __forceinline__ float ex2_fast (float x){ float r; asm("ex2.approx.ftz.f32 %0, %1;" : "=f"(r) : "f"(x)); return r; }
__device__ __forceinline__ float lg2_fast (float x){ float r; asm("lg2.approx.ftz.f32 %0, %1;" : "=f"(r) : "f"(x)); return r; }
__device__ __forceinline__ float rcp_fast (float x){ float r; asm("rcp.approx.ftz.f32 %0, %1;" : "=f"(r) : "f"(x)); return r; }
// softplus given pre-scaled (log2e) argument: log2(1 + 2^y)
__device__ __forceinline__ float sp_pre(float y){ return lg2_fast(1.0f + ex2_fast(y)); }
__device__ __forceinline__ float shflx(float v, int m){ return __shfl_xor_sync(0xffffffffu, v, m); }
__device__ __forceinline__ float shfli(float v, int s){ return __shfl_sync(0xffffffffu, v, s); }
}

// ONE battery per warp (32 lanes: hp 4/lane, hr 2/lane). R12's batch-4 stale
// pipeline (consume steps t..t+3, then build sets for t+4..t+7 at the newest
// soc; staleness 0..3) PLUS 2 warps per SMSP: the sibling warp fills the
// in-order stalls R12 left exposed (274 cy/step vs 144-cy MUFU floor at 45%
// issue). R13 proved ptxas won't interleave across blocks at high regcount —
// only the HW arbiter fills stalls reliably.
__global__ void __launch_bounds__(256, 1) dci_rollout(
    const float* __restrict__ gI, const float* __restrict__ gT, const float* __restrict__ soc0,
    const float* __restrict__ W1p, const float* __restrict__ b1p,
    const float* __restrict__ W2p, const float* __restrict__ b2p,
    const float* __restrict__ W1r, const float* __restrict__ b1r,
    const float* __restrict__ W2r, const float* __restrict__ b2r,
    float* __restrict__ out)
{
    const int lane = threadIdx.x & 31;
    const int bat  = (blockIdx.x * blockDim.x + threadIdx.x) >> 5;

    constexpr float LOG2E = 1.4426950408889634f;
    constexpr float LN2   = 0.6931471805599453f;
    constexpr float EPS   = 1e-6f;
    constexpr float KSOC  = -1.0f / 3600.0f;

    // --- weights into registers; W2 columns pre-scaled by log2e ---
    float w0[4], w1[4], w2[4], wb[4];
    float wx[4], wy[4], wz[4], wq[4];
#pragma unroll
    for (int k = 0; k < 4; ++k) {
        int u = lane + 32 * k;
        w0[k] = W1p[u]; w1[k] = W1p[128 + u]; w2[k] = W1p[256 + u]; wb[k] = b1p[u];
        float4 wp = reinterpret_cast<const float4*>(W2p)[u];   // [R0,R1,C1,Q] row u
        wx[k] = wp.x * LOG2E; wy[k] = wp.y * LOG2E; wz[k] = wp.z * LOG2E; wq[k] = wp.w * LOG2E;
    }
    float q0[2], q1[2], q2[2], qb[2], qw[2];
#pragma unroll
    for (int k = 0; k < 2; ++k) {
        int u = lane + 32 * k;
        q0[k] = W1r[u]; q1[k] = W1r[64 + u]; q2[k] = W1r[128 + u]; qb[k] = b1r[u];
        qw[k] = W2r[u];
    }
    float4 b2 = *reinterpret_cast<const float4*>(b2p);
    const float bx32 = b2.x * (LOG2E / 32.0f);
    const float by32 = b2.y * (LOG2E / 32.0f);
    const float bz32 = b2.z * (LOG2E / 32.0f);
    const float bq32 = b2.w * (LOG2E / 32.0f);
    const float br32 = b2r[0] * (1.0f / 32.0f);

    // packed-reduce lane role: quantity = lane&3 (0:R0, 1:R1, 2:C1, 3:resid)
    const int   qq    = lane & 3;
    const float sclq  = (qq == 0) ? 0.01f * LN2 : (qq == 1) ? 0.02f * LN2 : 2000.0f * LN2;
    const bool  isres = (qq == 3);
    const bool  oddq  = (lane & 1) != 0;
    const bool  hiq   = (lane & 2) != 0;

    float s0  = soc0[bat];
    float soc = (s0 == s0) ? s0 : 0.8f;   // NaN -> 0.8
    float v1  = 0.0f;

    const float* Iin = gI + bat * Hn;
    const float* Tin = gT + bat * Hn;
    float vkeep = 0.0f;
    float* orow = out + bat * Hn;

    // parameter sets for the next 4 steps
    float rqS[4], R0S[4], resS[4], iRCS[4], iC1S[4];
    float Icur[4];

    // build 4 sets from ONE soc argument and 4 (I,T) pairs; 4 chains interleaved
    auto makeSet4 = [&](float socA, const float* I4, const float* T4) {
        float h[4][4];
#pragma unroll
        for (int k = 0; k < 4; ++k)
#pragma unroll
            for (int j = 0; j < 4; ++j)
                h[j][k] = tanh_fast(fmaf(socA, w0[k],
                             fmaf(I4[j], w1[k], fmaf(T4[j], w2[k], wb[k]))));

        // Q partial trees (4 chains) + 5-stage interleaved butterflies
        float p3[4];
#pragma unroll
        for (int j = 0; j < 4; ++j)
            p3[j] = (fmaf(h[j][0], wq[0], bq32) + h[j][1] * wq[1])
                  + (h[j][2] * wq[2] + h[j][3] * wq[3]);
#pragma unroll
        for (int d = 1; d <= 16; d <<= 1)
#pragma unroll
            for (int j = 0; j < 4; ++j)
                p3[j] += shflx(p3[j], d);

        // hr heads (k-major: MUFU spread across chains)
        float pr[4] = {br32, br32, br32, br32};
#pragma unroll
        for (int k = 0; k < 2; ++k)
#pragma unroll
            for (int j = 0; j < 4; ++j)
                pr[j] = fmaf(tanh_fast(fmaf(socA, q0[k],
                              fmaf(I4[j], q1[k], fmaf(T4[j], q2[k], qb[k])))), qw[k], pr[j]);

        // param partials
        float p0[4], p1[4], p2[4];
#pragma unroll
        for (int j = 0; j < 4; ++j) {
            p0[j] = fmaf(h[j][0], wx[0], bx32);
            p1[j] = fmaf(h[j][0], wy[0], by32);
            p2[j] = fmaf(h[j][0], wz[0], bz32);
        }
#pragma unroll
        for (int k = 1; k < 4; ++k)
#pragma unroll
            for (int j = 0; j < 4; ++j) {
                p0[j] = fmaf(h[j][k], wx[k], p0[j]);
                p1[j] = fmaf(h[j][k], wy[k], p1[j]);
                p2[j] = fmaf(h[j][k], wz[k], p2[j]);
            }

        // packed 4-quantity reduce per chain: fold at xor1/xor2, share 4/8/16
        float w4[4];
#pragma unroll
        for (int j = 0; j < 4; ++j) {
            float sA = p0[j] + shflx(p0[j], 1);
            float sB = p1[j] + shflx(p1[j], 1);
            float sC = p2[j] + shflx(p2[j], 1);
            float sD = pr[j] + shflx(pr[j], 1);
            float u  = oddq ? sB : sA;
            float v  = oddq ? sD : sC;
            float su = u + shflx(u, 2);
            float sv = v + shflx(v, 2);
            w4[j] = hiq ? sv : su;
        }
#pragma unroll
        for (int d = 4; d <= 16; d <<= 1)
#pragma unroll
            for (int j = 0; j < 4; ++j)
                w4[j] += shflx(w4[j], d);

        float fin[4];
#pragma unroll
        for (int j = 0; j < 4; ++j)
            fin[j] = isres ? w4[j] : fmaf(sp_pre(w4[j]), sclq, EPS);
#pragma unroll
        for (int j = 0; j < 4; ++j)
            rqS[j] = rcp_fast(fmaf(sp_pre(p3[j]), 5.0f * LN2, EPS));
#pragma unroll
        for (int j = 0; j < 4; ++j) {
            R0S[j]    = shfli(fin[j], 0);
            float R1  = shfli(fin[j], 1);
            float C1  = shfli(fin[j], 2);
            resS[j]   = shfli(fin[j], 3);
            iRCS[j]   = rcp_fast(R1 * C1);
            iC1S[j]   = iRCS[j] * R1;            // 1/C1 = R1/(R1*C1)
        }
    };

    // ---- prologue: sets for steps 0..3, all at soc0 (step 0 exact) ----
    {
        float I4[4], T4[4];
#pragma unroll
        for (int j = 0; j < 4; ++j) { I4[j] = __ldg(Iin + j); T4[j] = __ldg(Tin + j); }
        makeSet4(soc, I4, T4);
#pragma unroll
        for (int j = 0; j < 4; ++j) Icur[j] = I4[j];
    }

#pragma unroll 1
    for (int t = 0; t < Hn; t += 4) {
        // ===== consume steps t..t+3 (serial but trivial) =====
#pragma unroll
        for (int j = 0; j < 4; ++j) {
            float Iv   = Icur[j];
            float socn = __saturatef(fmaf(Iv * KSOC, rqS[j], soc));
            float v1n  = fmaf(Iv, iC1S[j], fmaf(-v1, iRCS[j], v1));   // v1 - v1/(R1C1) + I/C1
            float ocv  = fmaf(fmaf(fmaf(0.3f, socn, -0.5f), socn, 1.2f), socn, 3.0f);
            float Vp   = (ocv - fmaf(Iv, R0S[j], v1n)) + resS[j];
            const int tt = t + j;
            if ((tt & 31) == lane) vkeep = Vp;
            if ((tt & 31) == 31)   orow[(tt & ~31) + lane] = vkeep;
            soc = socn; v1 = v1n;
        }

        // ===== loads for steps t+4..t+7 =====
        float I4[4], T4[4];
#pragma unroll
        for (int j = 0; j < 4; ++j) {
            const int i = (t + 4 + j) & (Hn - 1);    // wrap: final block unused
            I4[j] = __ldg(Iin + i);
            T4[j] = __ldg(Tin + i);
        }

        // ===== build next 4 sets at the newest soc: staleness 0..3 =====
        makeSet4(soc, I4, T4);
#pragma unroll
        for (int j = 0; j < 4; ++j) Icur[j] = I4[j];
    }
}

extern "C" void kernel_launch(void* const* d_in, const int* in_sizes, int n_in,
                              void* d_out, int out_size)
{
    // inputs: V(unused), I, Tz, soc0, W1p, b1p, W2p, b2p, W1r, b1r, W2r, b2r
    const float* I    = (const float*)d_in[1];
    const float* Tz   = (const float*)d_in[2];
    const float* soc0 = (const float*)d_in[3];
    const float* W1p  = (const float*)d_in[4];
    const float* b1p  = (const float*)d_in[5];
    const float* W2p  = (const float*)d_in[6];
    const float* b2p  = (const float*)d_in[7];
    const float* W1r  = (const float*)d_in[8];
    const float* b1r  = (const float*)d_in[9];
    const float* W2r  = (const float*)d_in[10];
    const float* b2r  = (const float*)d_in[11];
    float* out = (float*)d_out;

    // 1024 warps = 1024 batteries (1/warp); 128 blocks x 256 threads
    // -> uniform 2 warps/SMSP on 128 SMs: the HW arbiter (not ptxas) fills
    //    each warp's pipeline-stall windows with the sibling's instructions.
    dci_rollout<<<128, 256>>>(I, Tz, soc0, W1p, b1p, W2p, b2p,
                              W1r, b1r, W2r, b2r, out);
}

// round 15
// speedup vs baseline: 1.0234x; 1.0234x over previous
#include <cuda_runtime.h>

namespace {
constexpr int Hn = 1024;   // time steps

__device__ __forceinline__ float tanh_fast(float x){ float r; asm("tanh.approx.f32 %0, %1;" : "=f"(r) : "f"(x)); return r; }
__device__ __forceinline__ float ex2_fast (float x){ float r; asm("ex2.approx.ftz.f32 %0, %1;" : "=f"(r) : "f"(x)); return r; }
__device__ __forceinline__ float lg2_fast (float x){ float r; asm("lg2.approx.ftz.f32 %0, %1;" : "=f"(r) : "f"(x)); return r; }
__device__ __forceinline__ float rcp_fast (float x){ float r; asm("rcp.approx.ftz.f32 %0, %1;" : "=f"(r) : "f"(x)); return r; }
// softplus given pre-scaled (log2e) argument: log2(1 + 2^y)
__device__ __forceinline__ float sp_pre(float y){ return lg2_fast(1.0f + ex2_fast(y)); }
__device__ __forceinline__ float shflx(float v, int m){ return __shfl_xor_sync(0xffffffffu, v, m); }
__device__ __forceinline__ float shfli(float v, int s){ return __shfl_sync(0xffffffffu, v, s); }
}

// ONE battery per warp; 1024 warps -> uniform 2 warps/SMSP on 128 SMs (R14
// config, proven issue-bound at 59.7%). This round cuts per-warp issues:
// ALL FIVE reduced quantities (R0,R1,C1,Q,resid) ride ONE packed folded
// butterfly (12 SHFLs vs ~29), and one softplus per lane covers R0/R1/C1/Q
// (10 MUFU/warp-step). Staleness scheme unchanged from R12/R14 (build after
// consume at newest soc; staleness 0..3 -> rel_err ~1.8e-5).
__global__ void __launch_bounds__(256, 1) dci_rollout(
    const float* __restrict__ gI, const float* __restrict__ gT, const float* __restrict__ soc0,
    const float* __restrict__ W1p, const float* __restrict__ b1p,
    const float* __restrict__ W2p, const float* __restrict__ b2p,
    const float* __restrict__ W1r, const float* __restrict__ b1r,
    const float* __restrict__ W2r, const float* __restrict__ b2r,
    float* __restrict__ out)
{
    const int lane = threadIdx.x & 31;
    const int bat  = (blockIdx.x * blockDim.x + threadIdx.x) >> 5;

    constexpr float LOG2E = 1.4426950408889634f;
    constexpr float LN2   = 0.6931471805599453f;
    constexpr float EPS   = 1e-6f;
    constexpr float KSOC  = -1.0f / 3600.0f;

    // --- weights into registers; W2 columns pre-scaled by log2e ---
    float w0[4], w1[4], w2[4], wb[4];
    float wx[4], wy[4], wz[4], wq[4];
#pragma unroll
    for (int k = 0; k < 4; ++k) {
        int u = lane + 32 * k;
        w0[k] = W1p[u]; w1[k] = W1p[128 + u]; w2[k] = W1p[256 + u]; wb[k] = b1p[u];
        float4 wp = reinterpret_cast<const float4*>(W2p)[u];   // [R0,R1,C1,Q] row u
        wx[k] = wp.x * LOG2E; wy[k] = wp.y * LOG2E; wz[k] = wp.z * LOG2E; wq[k] = wp.w * LOG2E;
    }
    float q0[2], q1[2], q2[2], qb[2], qw[2];
#pragma unroll
    for (int k = 0; k < 2; ++k) {
        int u = lane + 32 * k;
        q0[k] = W1r[u]; q1[k] = W1r[64 + u]; q2[k] = W1r[128 + u]; qb[k] = b1r[u];
        qw[k] = W2r[u];
    }
    float4 b2 = *reinterpret_cast<const float4*>(b2p);
    const float bx32 = b2.x * (LOG2E / 32.0f);
    const float by32 = b2.y * (LOG2E / 32.0f);
    const float bz32 = b2.z * (LOG2E / 32.0f);
    const float bq32 = b2.w * (LOG2E / 32.0f);
    const float br32 = b2r[0] * (1.0f / 32.0f);

    // pack-5 lane role: lane&7 -> 0:R0 1:R1 2:C1 3:Q 4..7:resid
    const int   rr    = lane & 3;
    const float sclq  = (rr == 0) ? 0.01f * LN2 : (rr == 1) ? 0.02f * LN2
                      : (rr == 2) ? 2000.0f * LN2 : 5.0f * LN2;
    const bool  isres = (lane & 4) != 0;
    const bool  odd1  = (lane & 1) != 0;
    const bool  hi2   = (lane & 2) != 0;

    float s0  = soc0[bat];
    float soc = (s0 == s0) ? s0 : 0.8f;   // NaN -> 0.8
    float v1  = 0.0f;

    const float* Iin = gI + bat * Hn;
    const float* Tin = gT + bat * Hn;
    float vkeep = 0.0f;
    float* orow = out + bat * Hn;

    // parameter sets for the next 4 steps
    float rqS[4], R0S[4], resS[4], iRCS[4], iC1S[4];
    float Icur[4];

    // build 4 sets from ONE soc argument and 4 (I,T) pairs; 4 chains interleaved
    auto makeSet4 = [&](float socA, const float* I4, const float* T4) {
        float h[4][4];
#pragma unroll
        for (int k = 0; k < 4; ++k)
#pragma unroll
            for (int j = 0; j < 4; ++j)
                h[j][k] = tanh_fast(fmaf(socA, w0[k],
                             fmaf(I4[j], w1[k], fmaf(T4[j], w2[k], wb[k]))));

        // hr heads
        float pr[4] = {br32, br32, br32, br32};
#pragma unroll
        for (int k = 0; k < 2; ++k)
#pragma unroll
            for (int j = 0; j < 4; ++j)
                pr[j] = fmaf(tanh_fast(fmaf(socA, q0[k],
                              fmaf(I4[j], q1[k], fmaf(T4[j], q2[k], qb[k])))), qw[k], pr[j]);

        // partials: p0..p2 params, p3 = Q
        float p0[4], p1[4], p2[4], p3[4];
#pragma unroll
        for (int j = 0; j < 4; ++j) {
            p0[j] = fmaf(h[j][0], wx[0], bx32);
            p1[j] = fmaf(h[j][0], wy[0], by32);
            p2[j] = fmaf(h[j][0], wz[0], bz32);
            p3[j] = fmaf(h[j][0], wq[0], bq32);
        }
#pragma unroll
        for (int k = 1; k < 4; ++k)
#pragma unroll
            for (int j = 0; j < 4; ++j) {
                p0[j] = fmaf(h[j][k], wx[k], p0[j]);
                p1[j] = fmaf(h[j][k], wy[k], p1[j]);
                p2[j] = fmaf(h[j][k], wz[k], p2[j]);
                p3[j] = fmaf(h[j][k], wq[k], p3[j]);
            }

        // ---- pack-5 folded reduce (stage-major across the 4 chains) ----
        float xf[4], yf[4], ef[4];
#pragma unroll
        for (int j = 0; j < 4; ++j) {                 // xor1: fold {R0,R1},{C1,Q}
            float a1 = p0[j] + shflx(p0[j], 1);
            float b1 = p1[j] + shflx(p1[j], 1);
            float c1 = p2[j] + shflx(p2[j], 1);
            float d1 = p3[j] + shflx(p3[j], 1);
            ef[j]    = pr[j] + shflx(pr[j], 1);
            xf[j] = odd1 ? b1 : a1;
            yf[j] = odd1 ? d1 : c1;
        }
        float zf[4];
#pragma unroll
        for (int j = 0; j < 4; ++j) {                 // xor2
            xf[j] += shflx(xf[j], 2);
            yf[j] += shflx(yf[j], 2);
            ef[j] += shflx(ef[j], 2);
            zf[j] = hi2 ? yf[j] : xf[j];              // lane&3 carries R0/R1/C1/Q
        }
        float vf[4];
#pragma unroll
        for (int j = 0; j < 4; ++j) {                 // xor4, fold in resid
            zf[j] += shflx(zf[j], 4);
            ef[j] += shflx(ef[j], 4);
            vf[j] = isres ? ef[j] : zf[j];            // lane&7: 0..3 params, 4..7 resid
        }
#pragma unroll
        for (int j = 0; j < 4; ++j) vf[j] += shflx(vf[j], 8);
#pragma unroll
        for (int j = 0; j < 4; ++j) vf[j] += shflx(vf[j], 16);

        // finalize: ONE softplus per lane covers R0/R1/C1/Q; resid raw
        float fin[4];
#pragma unroll
        for (int j = 0; j < 4; ++j)
            fin[j] = isres ? vf[j] : fmaf(sp_pre(vf[j]), sclq, EPS);

#pragma unroll
        for (int j = 0; j < 4; ++j) {
            R0S[j]    = shfli(fin[j], 0);
            float R1  = shfli(fin[j], 1);
            float C1  = shfli(fin[j], 2);
            rqS[j]    = rcp_fast(shfli(fin[j], 3));
            resS[j]   = shfli(fin[j], 4);
            iRCS[j]   = rcp_fast(R1 * C1);
            iC1S[j]   = iRCS[j] * R1;                 // 1/C1 = R1/(R1*C1)
        }
    };

    // ---- prologue: sets for steps 0..3, all at soc0 (step 0 exact) ----
    {
        float I4[4], T4[4];
#pragma unroll
        for (int j = 0; j < 4; ++j) { I4[j] = __ldg(Iin + j); T4[j] = __ldg(Tin + j); }
        makeSet4(soc, I4, T4);
#pragma unroll
        for (int j = 0; j < 4; ++j) Icur[j] = I4[j];
    }

#pragma unroll 1
    for (int t = 0; t < Hn; t += 4) {
        // ===== consume steps t..t+3 (serial but trivial) =====
#pragma unroll
        for (int j = 0; j < 4; ++j) {
            float Iv   = Icur[j];
            float socn = __saturatef(fmaf(Iv * KSOC, rqS[j], soc));
            float v1n  = fmaf(Iv, iC1S[j], fmaf(-v1, iRCS[j], v1));   // v1 - v1/(R1C1) + I/C1
            float ocv  = fmaf(fmaf(fmaf(0.3f, socn, -0.5f), socn, 1.2f), socn, 3.0f);
            float Vp   = (ocv - fmaf(Iv, R0S[j], v1n)) + resS[j];
            const int tt = t + j;
            if ((tt & 31) == lane) vkeep = Vp;
            if ((tt & 31) == 31)   orow[(tt & ~31) + lane] = vkeep;
            soc = socn; v1 = v1n;
        }

        // ===== loads for steps t+4..t+7 =====
        float I4[4], T4[4];
#pragma unroll
        for (int j = 0; j < 4; ++j) {
            const int i = (t + 4 + j) & (Hn - 1);    // wrap: final block unused
            I4[j] = __ldg(Iin + i);
            T4[j] = __ldg(Tin + i);
        }

        // ===== build next 4 sets at the newest soc: staleness 0..3 =====
        makeSet4(soc, I4, T4);
#pragma unroll
        for (int j = 0; j < 4; ++j) Icur[j] = I4[j];
    }
}

extern "C" void kernel_launch(void* const* d_in, const int* in_sizes, int n_in,
                              void* d_out, int out_size)
{
    // inputs: V(unused), I, Tz, soc0, W1p, b1p, W2p, b2p, W1r, b1r, W2r, b2r
    const float* I    = (const float*)d_in[1];
    const float* Tz   = (const float*)d_in[2];
    const float* soc0 = (const float*)d_in[3];
    const float* W1p  = (const float*)d_in[4];
    const float* b1p  = (const float*)d_in[5];
    const float* W2p  = (const float*)d_in[6];
    const float* b2p  = (const float*)d_in[7];
    const float* W1r  = (const float*)d_in[8];
    const float* b1r  = (const float*)d_in[9];
    const float* W2r  = (const float*)d_in[10];
    const float* b2r  = (const float*)d_in[11];
    float* out = (float*)d_out;

    // 1024 warps = 1024 batteries (1/warp); 128 blocks x 256 threads
    // -> uniform 2 warps/SMSP on 128 SMs; per-warp issue count minimized so
    //    the 2-warp issue stream approaches the SMSP's 1/cy limit.
    dci_rollout<<<128, 256>>>(I, Tz, soc0, W1p, b1p, W2p, b2p,
                              W1r, b1r, W2r, b2r, out);
}

// round 16
// speedup vs baseline: 1.1036x; 1.0783x over previous
#include <cuda_runtime.h>

namespace {
constexpr int Hn = 1024;   // time steps

__device__ __forceinline__ float tanh_fast(float x){ float r; asm("tanh.approx.f32 %0, %1;" : "=f"(r) : "f"(x)); return r; }
__device__ __forceinline__ float ex2_fast (float x){ float r; asm("ex2.approx.ftz.f32 %0, %1;" : "=f"(r) : "f"(x)); return r; }
__device__ __forceinline__ float lg2_fast (float x){ float r; asm("lg2.approx.ftz.f32 %0, %1;" : "=f"(r) : "f"(x)); return r; }
__device__ __forceinline__ float rcp_fast (float x){ float r; asm("rcp.approx.ftz.f32 %0, %1;" : "=f"(r) : "f"(x)); return r; }
// softplus given pre-scaled (log2e) argument: log2(1 + 2^y)
__device__ __forceinline__ float sp_pre(float y){ return lg2_fast(1.0f + ex2_fast(y)); }
__device__ __forceinline__ float shflx(float v, int m){ return __shfl_xor_sync(0xffffffffu, v, m); }
__device__ __forceinline__ float shfli(float v, int s){ return __shfl_sync(0xffffffffu, v, s); }
}

// ONE battery per warp; 1024 warps -> uniform 2 warps/SMSP on 128 SMs.
// BATCH-8 stale pipeline: consume steps t..t+7, then ONE makeSet8 builds the
// sets for t+8..t+15 at the newest soc (staleness 0..7, avg 3.5 -> ~2.6e-5,
// R11-verified). Transient-h: each chain's tanh results fold immediately into
// its partials, so chain j's reduce overlaps chain j+1's MUFU work — the
// build's critical path no longer spans all 48 tanhs (R12's 305-cy/step
// exposure), and live registers stay ~150.
__global__ void __launch_bounds__(256, 1) dci_rollout(
    const float* __restrict__ gI, const float* __restrict__ gT, const float* __restrict__ soc0,
    const float* __restrict__ W1p, const float* __restrict__ b1p,
    const float* __restrict__ W2p, const float* __restrict__ b2p,
    const float* __restrict__ W1r, const float* __restrict__ b1r,
    const float* __restrict__ W2r, const float* __restrict__ b2r,
    float* __restrict__ out)
{
    const int lane = threadIdx.x & 31;
    const int bat  = (blockIdx.x * blockDim.x + threadIdx.x) >> 5;

    constexpr float LOG2E = 1.4426950408889634f;
    constexpr float LN2   = 0.6931471805599453f;
    constexpr float EPS   = 1e-6f;
    constexpr float KSOC  = -1.0f / 3600.0f;

    // --- weights into registers; W2 columns pre-scaled by log2e ---
    float w0[4], w1[4], w2[4], wb[4];
    float wx[4], wy[4], wz[4], wq[4];
#pragma unroll
    for (int k = 0; k < 4; ++k) {
        int u = lane + 32 * k;
        w0[k] = W1p[u]; w1[k] = W1p[128 + u]; w2[k] = W1p[256 + u]; wb[k] = b1p[u];
        float4 wp = reinterpret_cast<const float4*>(W2p)[u];   // [R0,R1,C1,Q] row u
        wx[k] = wp.x * LOG2E; wy[k] = wp.y * LOG2E; wz[k] = wp.z * LOG2E; wq[k] = wp.w * LOG2E;
    }
    float q0[2], q1[2], q2[2], qb[2], qw[2];
#pragma unroll
    for (int k = 0; k < 2; ++k) {
        int u = lane + 32 * k;
        q0[k] = W1r[u]; q1[k] = W1r[64 + u]; q2[k] = W1r[128 + u]; qb[k] = b1r[u];
        qw[k] = W2r[u];
    }
    float4 b2 = *reinterpret_cast<const float4*>(b2p);
    const float bx32 = b2.x * (LOG2E / 32.0f);
    const float by32 = b2.y * (LOG2E / 32.0f);
    const float bz32 = b2.z * (LOG2E / 32.0f);
    const float bq32 = b2.w * (LOG2E / 32.0f);
    const float br32 = b2r[0] * (1.0f / 32.0f);

    // pack-5 lane role: lane&7 -> 0:R0 1:R1 2:C1 3:Q 4..7:resid
    const int   rr    = lane & 3;
    const float sclq  = (rr == 0) ? 0.01f * LN2 : (rr == 1) ? 0.02f * LN2
                      : (rr == 2) ? 2000.0f * LN2 : 5.0f * LN2;
    const bool  isres = (lane & 4) != 0;
    const bool  odd1  = (lane & 1) != 0;
    const bool  hi2   = (lane & 2) != 0;

    float s0  = soc0[bat];
    float soc = (s0 == s0) ? s0 : 0.8f;   // NaN -> 0.8
    float v1  = 0.0f;

    const float* Iin = gI + bat * Hn;
    const float* Tin = gT + bat * Hn;
    float vkeep = 0.0f;
    float* orow = out + bat * Hn;

    // parameter sets for the next 8 steps
    float rqS[8], R0S[8], resS[8], iRCS[8], iC1S[8];
    float Icur[8];

    // build 8 sets from ONE soc argument and 8 (I,T) pairs.
    // Chain-local: tanh -> immediate partial accumulation (h transient).
    auto makeSet8 = [&](float socA, const float* I8, const float* T8) {
        float p0[8], p1[8], p2[8], p3[8], pr[8];
#pragma unroll
        for (int j = 0; j < 8; ++j) {
            float h0 = tanh_fast(fmaf(socA, w0[0], fmaf(I8[j], w1[0], fmaf(T8[j], w2[0], wb[0]))));
            float h1 = tanh_fast(fmaf(socA, w0[1], fmaf(I8[j], w1[1], fmaf(T8[j], w2[1], wb[1]))));
            float h2 = tanh_fast(fmaf(socA, w0[2], fmaf(I8[j], w1[2], fmaf(T8[j], w2[2], wb[2]))));
            float h3 = tanh_fast(fmaf(socA, w0[3], fmaf(I8[j], w1[3], fmaf(T8[j], w2[3], wb[3]))));
            p0[j] = fmaf(h3, wx[3], fmaf(h2, wx[2], fmaf(h1, wx[1], fmaf(h0, wx[0], bx32))));
            p1[j] = fmaf(h3, wy[3], fmaf(h2, wy[2], fmaf(h1, wy[1], fmaf(h0, wy[0], by32))));
            p2[j] = fmaf(h3, wz[3], fmaf(h2, wz[2], fmaf(h1, wz[1], fmaf(h0, wz[0], bz32))));
            p3[j] = fmaf(h3, wq[3], fmaf(h2, wq[2], fmaf(h1, wq[1], fmaf(h0, wq[0], bq32))));
            float e0 = tanh_fast(fmaf(socA, q0[0], fmaf(I8[j], q1[0], fmaf(T8[j], q2[0], qb[0]))));
            float e1 = tanh_fast(fmaf(socA, q0[1], fmaf(I8[j], q1[1], fmaf(T8[j], q2[1], qb[1]))));
            pr[j] = fmaf(e1, qw[1], fmaf(e0, qw[0], br32));
        }

        // ---- pack-5 folded reduce, stage-major across the 8 chains ----
        float xf[8], yf[8], ef[8];
#pragma unroll
        for (int j = 0; j < 8; ++j) {                 // xor1: fold {R0,R1},{C1,Q}
            float a1 = p0[j] + shflx(p0[j], 1);
            float b1 = p1[j] + shflx(p1[j], 1);
            float c1 = p2[j] + shflx(p2[j], 1);
            float d1 = p3[j] + shflx(p3[j], 1);
            ef[j]    = pr[j] + shflx(pr[j], 1);
            xf[j] = odd1 ? b1 : a1;
            yf[j] = odd1 ? d1 : c1;
        }
        float vf[8];
#pragma unroll
        for (int j = 0; j < 8; ++j) {                 // xor2
            xf[j] += shflx(xf[j], 2);
            yf[j] += shflx(yf[j], 2);
            ef[j] += shflx(ef[j], 2);
            vf[j] = hi2 ? yf[j] : xf[j];              // lane&3 carries R0/R1/C1/Q
        }
#pragma unroll
        for (int j = 0; j < 8; ++j) {                 // xor4, fold in resid
            vf[j] += shflx(vf[j], 4);
            ef[j] += shflx(ef[j], 4);
            vf[j] = isres ? ef[j] : vf[j];            // lane&7: 0..3 params, 4..7 resid
        }
#pragma unroll
        for (int j = 0; j < 8; ++j) vf[j] += shflx(vf[j], 8);
#pragma unroll
        for (int j = 0; j < 8; ++j) vf[j] += shflx(vf[j], 16);

        // finalize: ONE softplus per lane covers R0/R1/C1/Q; resid raw
#pragma unroll
        for (int j = 0; j < 8; ++j) {
            float fin = isres ? vf[j] : fmaf(sp_pre(vf[j]), sclq, EPS);
            R0S[j]    = shfli(fin, 0);
            float R1  = shfli(fin, 1);
            float C1  = shfli(fin, 2);
            rqS[j]    = rcp_fast(shfli(fin, 3));
            resS[j]   = shfli(fin, 4);
            iRCS[j]   = rcp_fast(R1 * C1);
            iC1S[j]   = iRCS[j] * R1;                 // 1/C1 = R1/(R1*C1)
        }
    };

    // ---- prologue: sets for steps 0..7, all at soc0 (step 0 exact) ----
    {
        float I8[8], T8[8];
#pragma unroll
        for (int j = 0; j < 8; ++j) { I8[j] = __ldg(Iin + j); T8[j] = __ldg(Tin + j); }
        makeSet8(soc, I8, T8);
#pragma unroll
        for (int j = 0; j < 8; ++j) Icur[j] = I8[j];
    }

#pragma unroll 1
    for (int t = 0; t < Hn; t += 8) {
        // ===== consume steps t..t+7 (serial but trivial) =====
#pragma unroll
        for (int j = 0; j < 8; ++j) {
            float Iv   = Icur[j];
            float socn = __saturatef(fmaf(Iv * KSOC, rqS[j], soc));
            float v1n  = fmaf(Iv, iC1S[j], fmaf(-v1, iRCS[j], v1));   // v1 - v1/(R1C1) + I/C1
            float ocv  = fmaf(fmaf(fmaf(0.3f, socn, -0.5f), socn, 1.2f), socn, 3.0f);
            float Vp   = (ocv - fmaf(Iv, R0S[j], v1n)) + resS[j];
            const int tt = t + j;
            if ((tt & 31) == lane) vkeep = Vp;
            if ((tt & 31) == 31)   orow[(tt & ~31) + lane] = vkeep;
            soc = socn; v1 = v1n;
        }

        // ===== loads for steps t+8..t+15 =====
        float I8[8], T8[8];
#pragma unroll
        for (int j = 0; j < 8; ++j) {
            const int i = (t + 8 + j) & (Hn - 1);    // wrap: final block unused
            I8[j] = __ldg(Iin + i);
            T8[j] = __ldg(Tin + i);
        }

        // ===== build next 8 sets at the newest soc: staleness 0..7 =====
        makeSet8(soc, I8, T8);
#pragma unroll
        for (int j = 0; j < 8; ++j) Icur[j] = I8[j];
    }
}

extern "C" void kernel_launch(void* const* d_in, const int* in_sizes, int n_in,
                              void* d_out, int out_size)
{
    // inputs: V(unused), I, Tz, soc0, W1p, b1p, W2p, b2p, W1r, b1r, W2r, b2r
    const float* I    = (const float*)d_in[1];
    const float* Tz   = (const float*)d_in[2];
    const float* soc0 = (const float*)d_in[3];
    const float* W1p  = (const float*)d_in[4];
    const float* b1p  = (const float*)d_in[5];
    const float* W2p  = (const float*)d_in[6];
    const float* b2p  = (const float*)d_in[7];
    const float* W1r  = (const float*)d_in[8];
    const float* b1r  = (const float*)d_in[9];
    const float* W2r  = (const float*)d_in[10];
    const float* b2r  = (const float*)d_in[11];
    float* out = (float*)d_out;

    // 1024 warps = 1024 batteries (1/warp); 128 blocks x 256 threads
    // -> uniform 2 warps/SMSP on 128 SMs. Batch-8 amortizes one build's
    //    latency tail over 8 steps; the sibling warp fills what's left.
    dci_rollout<<<128, 256>>>(I, Tz, soc0, W1p, b1p, W2p, b2p,
                              W1r, b1r, W2r, b2r, out);
}

// round 17
// speedup vs baseline: 1.1974x; 1.0850x over previous
#include <cuda_runtime.h>

namespace {
constexpr int Hn = 1024;   // time steps

__device__ __forceinline__ float tanh_fast(float x){ float r; asm("tanh.approx.f32 %0, %1;" : "=f"(r) : "f"(x)); return r; }
__device__ __forceinline__ float ex2_fast (float x){ float r; asm("ex2.approx.ftz.f32 %0, %1;" : "=f"(r) : "f"(x)); return r; }
__device__ __forceinline__ float lg2_fast (float x){ float r; asm("lg2.approx.ftz.f32 %0, %1;" : "=f"(r) : "f"(x)); return r; }
__device__ __forceinline__ float rcp_fast (float x){ float r; asm("rcp.approx.ftz.f32 %0, %1;" : "=f"(r) : "f"(x)); return r; }
// softplus given pre-scaled (log2e) argument: log2(1 + 2^y)
__device__ __forceinline__ float sp_pre(float y){ return lg2_fast(1.0f + ex2_fast(y)); }
__device__ __forceinline__ float shflx(float v, int m){ return __shfl_xor_sync(0xffffffffu, v, m); }
__device__ __forceinline__ float shfli(float v, int s){ return __shfl_sync(0xffffffffu, v, s); }
}

// 2 batteries/warp, 16 lanes/battery (lowest issue+MUFU per battery-step) +
// BATCH-8 stale pipeline + transient-h build (R16's exposure cut) + pack-5
// folded reduce over the 16-lane group (one softplus per lane covers all four
// softplus'd params). 1 warp/SMSP on 128 SMs. Staleness 0..7 (avg 3.5) ->
// rel_err ~3e-5 (R16-verified).
__global__ void __launch_bounds__(128, 1) dci_rollout(
    const float* __restrict__ gI, const float* __restrict__ gT, const float* __restrict__ soc0,
    const float* __restrict__ W1p, const float* __restrict__ b1p,
    const float* __restrict__ W2p, const float* __restrict__ b2p,
    const float* __restrict__ W1r, const float* __restrict__ b1r,
    const float* __restrict__ W2r, const float* __restrict__ b2r,
    float* __restrict__ out)
{
    const int lane = threadIdx.x & 31;
    const int g    = lane & 15;
    const int base = lane & 16;
    const int bat  = ((blockIdx.x * blockDim.x + threadIdx.x) >> 5) * 2 + (lane >> 4);

    constexpr float LOG2E = 1.4426950408889634f;
    constexpr float LN2   = 0.6931471805599453f;
    constexpr float EPS   = 1e-6f;
    constexpr float KSOC  = -1.0f / 3600.0f;

    // --- weights into registers; W2 columns pre-scaled by log2e ---
    float w0[8], w1[8], w2[8], wb[8];
    float wx[8], wy[8], wz[8], wq[8];
#pragma unroll
    for (int k = 0; k < 8; ++k) {
        int u = g + 16 * k;
        w0[k] = W1p[u]; w1[k] = W1p[128 + u]; w2[k] = W1p[256 + u]; wb[k] = b1p[u];
        float4 wp = reinterpret_cast<const float4*>(W2p)[u];   // [R0,R1,C1,Q] row u
        wx[k] = wp.x * LOG2E; wy[k] = wp.y * LOG2E; wz[k] = wp.z * LOG2E; wq[k] = wp.w * LOG2E;
    }
    float q0[4], q1[4], q2[4], qb[4], qw[4];
#pragma unroll
    for (int k = 0; k < 4; ++k) {
        int u = g + 16 * k;
        q0[k] = W1r[u]; q1[k] = W1r[64 + u]; q2[k] = W1r[128 + u]; qb[k] = b1r[u];
        qw[k] = W2r[u];
    }
    float4 b2 = *reinterpret_cast<const float4*>(b2p);
    const float bx16 = b2.x * (LOG2E / 16.0f);
    const float by16 = b2.y * (LOG2E / 16.0f);
    const float bz16 = b2.z * (LOG2E / 16.0f);
    const float bq16 = b2.w * (LOG2E / 16.0f);
    const float br16 = b2r[0] * (1.0f / 16.0f);

    // pack-5 lane role within the 16-lane group: g&7 -> 0:R0 1:R1 2:C1 3:Q 4..7:resid
    const int   rr    = g & 3;
    const float sclq  = (rr == 0) ? 0.01f * LN2 : (rr == 1) ? 0.02f * LN2
                      : (rr == 2) ? 2000.0f * LN2 : 5.0f * LN2;
    const bool  isres = (g & 4) != 0;
    const bool  odd1  = (g & 1) != 0;
    const bool  hi2   = (g & 2) != 0;

    float s0  = soc0[bat];
    float soc = (s0 == s0) ? s0 : 0.8f;   // NaN -> 0.8
    float v1  = 0.0f;

    const float* Iin = gI + bat * Hn;
    const float* Tin = gT + bat * Hn;
    float vkeep = 0.0f;
    float* orow = out + bat * Hn;

    // parameter sets for the next 8 steps (I8/T8 double as the consume inputs)
    float rqS[8], R0S[8], resS[8], iRCS[8], iC1S[8];
    float I8[8], T8[8];

    // build 8 sets from ONE soc argument using I8/T8; transient-h chains.
    auto makeSet8 = [&](float socA) {
        float p0[8], p1[8], p2[8], p3[8], pr[8];
#pragma unroll
        for (int j = 0; j < 8; ++j) {
            float t0 = tanh_fast(fmaf(socA, w0[0], fmaf(I8[j], w1[0], fmaf(T8[j], w2[0], wb[0]))));
            float t1 = tanh_fast(fmaf(socA, w0[1], fmaf(I8[j], w1[1], fmaf(T8[j], w2[1], wb[1]))));
            float t2 = tanh_fast(fmaf(socA, w0[2], fmaf(I8[j], w1[2], fmaf(T8[j], w2[2], wb[2]))));
            float t3 = tanh_fast(fmaf(socA, w0[3], fmaf(I8[j], w1[3], fmaf(T8[j], w2[3], wb[3]))));
            float t4 = tanh_fast(fmaf(socA, w0[4], fmaf(I8[j], w1[4], fmaf(T8[j], w2[4], wb[4]))));
            float t5 = tanh_fast(fmaf(socA, w0[5], fmaf(I8[j], w1[5], fmaf(T8[j], w2[5], wb[5]))));
            float t6 = tanh_fast(fmaf(socA, w0[6], fmaf(I8[j], w1[6], fmaf(T8[j], w2[6], wb[6]))));
            float t7 = tanh_fast(fmaf(socA, w0[7], fmaf(I8[j], w1[7], fmaf(T8[j], w2[7], wb[7]))));
            p0[j] = fmaf(t7,wx[7],fmaf(t6,wx[6],fmaf(t5,wx[5],fmaf(t4,wx[4],
                    fmaf(t3,wx[3],fmaf(t2,wx[2],fmaf(t1,wx[1],fmaf(t0,wx[0],bx16))))))));
            p1[j] = fmaf(t7,wy[7],fmaf(t6,wy[6],fmaf(t5,wy[5],fmaf(t4,wy[4],
                    fmaf(t3,wy[3],fmaf(t2,wy[2],fmaf(t1,wy[1],fmaf(t0,wy[0],by16))))))));
            p2[j] = fmaf(t7,wz[7],fmaf(t6,wz[6],fmaf(t5,wz[5],fmaf(t4,wz[4],
                    fmaf(t3,wz[3],fmaf(t2,wz[2],fmaf(t1,wz[1],fmaf(t0,wz[0],bz16))))))));
            p3[j] = fmaf(t7,wq[7],fmaf(t6,wq[6],fmaf(t5,wq[5],fmaf(t4,wq[4],
                    fmaf(t3,wq[3],fmaf(t2,wq[2],fmaf(t1,wq[1],fmaf(t0,wq[0],bq16))))))));
            float e0 = tanh_fast(fmaf(socA, q0[0], fmaf(I8[j], q1[0], fmaf(T8[j], q2[0], qb[0]))));
            float e1 = tanh_fast(fmaf(socA, q0[1], fmaf(I8[j], q1[1], fmaf(T8[j], q2[1], qb[1]))));
            float e2 = tanh_fast(fmaf(socA, q0[2], fmaf(I8[j], q1[2], fmaf(T8[j], q2[2], qb[2]))));
            float e3 = tanh_fast(fmaf(socA, q0[3], fmaf(I8[j], q1[3], fmaf(T8[j], q2[3], qb[3]))));
            pr[j] = fmaf(e3, qw[3], fmaf(e2, qw[2], fmaf(e1, qw[1], fmaf(e0, qw[0], br16))));
        }

        // ---- pack-5 folded reduce over the 16-lane group (stage-major) ----
        float xf[8], yf[8], ef[8];
#pragma unroll
        for (int j = 0; j < 8; ++j) {                 // xor1: fold {R0,R1},{C1,Q}
            float a1 = p0[j] + shflx(p0[j], 1);
            float b1 = p1[j] + shflx(p1[j], 1);
            float c1 = p2[j] + shflx(p2[j], 1);
            float d1 = p3[j] + shflx(p3[j], 1);
            ef[j]    = pr[j] + shflx(pr[j], 1);
            xf[j] = odd1 ? b1 : a1;
            yf[j] = odd1 ? d1 : c1;
        }
        float vf[8];
#pragma unroll
        for (int j = 0; j < 8; ++j) {                 // xor2
            xf[j] += shflx(xf[j], 2);
            yf[j] += shflx(yf[j], 2);
            ef[j] += shflx(ef[j], 2);
            vf[j] = hi2 ? yf[j] : xf[j];              // g&3 carries R0/R1/C1/Q
        }
#pragma unroll
        for (int j = 0; j < 8; ++j) {                 // xor4, fold in resid
            vf[j] += shflx(vf[j], 4);
            ef[j] += shflx(ef[j], 4);
            vf[j] = isres ? ef[j] : vf[j];            // g&7: 0..3 params, 4..7 resid
        }
#pragma unroll
        for (int j = 0; j < 8; ++j) vf[j] += shflx(vf[j], 8);   // full 16-lane sums

        // finalize: ONE softplus per lane; gather per set
#pragma unroll
        for (int j = 0; j < 8; ++j) {
            float fin = isres ? vf[j] : fmaf(sp_pre(vf[j]), sclq, EPS);
            R0S[j]    = shfli(fin, base | 0);
            float R1  = shfli(fin, base | 1);
            float C1  = shfli(fin, base | 2);
            rqS[j]    = rcp_fast(shfli(fin, base | 3));
            resS[j]   = shfli(fin, base | 4);
            iRCS[j]   = rcp_fast(R1 * C1);
            iC1S[j]   = iRCS[j] * R1;                 // 1/C1 = R1/(R1*C1)
        }
    };

    // ---- prologue: sets for steps 0..7, all at soc0 (step 0 exact) ----
#pragma unroll
    for (int j = 0; j < 8; ++j) { I8[j] = __ldg(Iin + j); T8[j] = __ldg(Tin + j); }
    makeSet8(soc);

#pragma unroll 1
    for (int t = 0; t < Hn; t += 8) {
        // ===== consume steps t..t+7 (serial but trivial) =====
#pragma unroll
        for (int j = 0; j < 8; ++j) {
            float Iv   = I8[j];
            float socn = __saturatef(fmaf(Iv * KSOC, rqS[j], soc));
            float v1n  = fmaf(Iv, iC1S[j], fmaf(-v1, iRCS[j], v1));   // v1 - v1/(R1C1) + I/C1
            float ocv  = fmaf(fmaf(fmaf(0.3f, socn, -0.5f), socn, 1.2f), socn, 3.0f);
            float Vp   = (ocv - fmaf(Iv, R0S[j], v1n)) + resS[j];
            const int tt = t + j;
            if ((tt & 15) == g)  vkeep = Vp;
            if ((tt & 15) == 15) orow[(tt & ~15) + g] = vkeep;
            soc = socn; v1 = v1n;
        }

        // ===== loads for steps t+8..t+15 =====
#pragma unroll
        for (int j = 0; j < 8; ++j) {
            const int i = (t + 8 + j) & (Hn - 1);    // wrap: final block unused
            I8[j] = __ldg(Iin + i);
            T8[j] = __ldg(Tin + i);
        }

        // ===== build next 8 sets at the newest soc: staleness 0..7 =====
        makeSet8(soc);
    }
}

extern "C" void kernel_launch(void* const* d_in, const int* in_sizes, int n_in,
                              void* d_out, int out_size)
{
    // inputs: V(unused), I, Tz, soc0, W1p, b1p, W2p, b2p, W1r, b1r, W2r, b2r
    const float* I    = (const float*)d_in[1];
    const float* Tz   = (const float*)d_in[2];
    const float* soc0 = (const float*)d_in[3];
    const float* W1p  = (const float*)d_in[4];
    const float* b1p  = (const float*)d_in[5];
    const float* W2p  = (const float*)d_in[6];
    const float* b2p  = (const float*)d_in[7];
    const float* W1r  = (const float*)d_in[8];
    const float* b1r  = (const float*)d_in[9];
    const float* W2r  = (const float*)d_in[10];
    const float* b2r  = (const float*)d_in[11];
    float* out = (float*)d_out;

    // 512 warps = 1024 batteries (2/warp); 128 blocks x 128 threads
    // -> 1 warp/SMSP on 128 SMs; 2-bat/warp minimizes issues+MUFU per battery,
    //    batch-8 + transient-h minimizes exposed build latency.
    dci_rollout<<<128, 128>>>(I, Tz, soc0, W1p, b1p, W2p, b2p,
                              W1r, b1r, W2r, b2r, out);
}